// round 12
// baseline (speedup 1.0000x reference)
#include <cuda_runtime.h>
#include <math.h>
#include <stdint.h>

#define NTOK 16384
#define DIMV 1024
#define NH 4
#define HDV 256
#define EPSV 1e-5f
#define DEPTH_SCALE 0.40824829046386296f

// ---------------- scratch (device globals; no allocation) ----------------
__device__ __align__(16) float g_cat[(size_t)NH * NTOK * 512];     // [H][N][2HD]
__device__ __align__(16) float g_gamma[(size_t)NH * NTOK * HDV];   // [H][N][HD]
__device__ __align__(16) float g_dt[(size_t)NTOK * NH];            // [N][H]
__device__ __align__(16) float g_xvcat[(size_t)2 * NTOK * DIMV];   // x_cat then v_cat (tf32-rounded)
__device__ __align__(16) float g_wo[(size_t)2 * DIMV * DIMV];      // Wo_x, Wo_v tf32-rounded

// ---------------- tf32 helpers ----------------
__device__ __forceinline__ float tf32_rna(float x) {
    uint32_t u;
    asm("cvt.rna.tf32.f32 %0, %1;" : "=r"(u) : "f"(x));
    return __uint_as_float(u);
}

__device__ __forceinline__ void mma_tf32(float* d, const float* a, const float* b) {
    asm volatile(
        "mma.sync.aligned.m16n8k8.row.col.f32.tf32.tf32.f32 "
        "{%0,%1,%2,%3}, {%4,%5,%6,%7}, {%8,%9}, {%0,%1,%2,%3};\n"
        : "+f"(d[0]), "+f"(d[1]), "+f"(d[2]), "+f"(d[3])
        : "r"(__float_as_uint(a[0])), "r"(__float_as_uint(a[1])),
          "r"(__float_as_uint(a[2])), "r"(__float_as_uint(a[3])),
          "r"(__float_as_uint(b[0])), "r"(__float_as_uint(b[1])));
}

__device__ __forceinline__ void cp16(void* smem, const void* g) {
    uint32_t s = (uint32_t)__cvta_generic_to_shared(smem);
    asm volatile("cp.async.cg.shared.global [%0], [%1], 16;\n" :: "r"(s), "l"(g));
}
#define CP_COMMIT() asm volatile("cp.async.commit_group;\n" ::)
#define CP_WAIT1()  asm volatile("cp.async.wait_group 1;\n" ::)

// =========================================================================
// K0: round Wo_x and Wo_v to tf32 (RNA) into contiguous g_wo — ONE launch
// =========================================================================
__global__ __launch_bounds__(256) void k0_round2(const float* __restrict__ srcA,
                                                 const float* __restrict__ srcB,
                                                 float* __restrict__ dst, int n4half)
{
    int i = blockIdx.x * 256 + threadIdx.x;
    if (i < n4half) {
        float4 a = *(const float4*)(srcA + (size_t)i * 4);
        a.x = tf32_rna(a.x); a.y = tf32_rna(a.y);
        a.z = tf32_rna(a.z); a.w = tf32_rna(a.w);
        *(float4*)(dst + (size_t)i * 4) = a;
        float4 b = *(const float4*)(srcB + (size_t)i * 4);
        b.x = tf32_rna(b.x); b.y = tf32_rna(b.y);
        b.z = tf32_rna(b.z); b.w = tf32_rna(b.w);
        *(float4*)(dst + (size_t)n4half * 4 + (size_t)i * 4) = b;
    }
}

// =========================================================================
// K1: LayerNorm + gate (R4-proven block-per-token form)
// =========================================================================
__global__ __launch_bounds__(256) void k1_ln_gate(
    const float* __restrict__ x, const float* __restrict__ v,
    const float* __restrict__ lxg, const float* __restrict__ lxb,
    const float* __restrict__ lvg, const float* __restrict__ lvb,
    const float* __restrict__ gw, const float* __restrict__ gb,
    const float* __restrict__ dtp)
{
    size_t tok = blockIdx.x;
    int tid = threadIdx.x, lane = tid & 31, w = tid >> 5;

    const float4 x4 = *(const float4*)(x + tok * DIMV + tid * 4);
    const float4 v4 = *(const float4*)(v + tok * DIMV + tid * 4);

    float sx  = x4.x + x4.y + x4.z + x4.w;
    float sxx = x4.x*x4.x + x4.y*x4.y + x4.z*x4.z + x4.w*x4.w;
    float sv  = v4.x + v4.y + v4.z + v4.w;
    float svv = v4.x*v4.x + v4.y*v4.y + v4.z*v4.z + v4.w*v4.w;
    #pragma unroll
    for (int o = 16; o; o >>= 1) {
        sx  += __shfl_xor_sync(0xffffffffu, sx,  o);
        sxx += __shfl_xor_sync(0xffffffffu, sxx, o);
        sv  += __shfl_xor_sync(0xffffffffu, sv,  o);
        svv += __shfl_xor_sync(0xffffffffu, svv, o);
    }
    __shared__ float4 red[8];
    if (lane == 0) red[w] = make_float4(sx, sxx, sv, svv);
    __syncthreads();
    float tsx = 0.f, tsxx = 0.f, tsv = 0.f, tsvv = 0.f;
    #pragma unroll
    for (int i = 0; i < 8; i++) {
        float4 r = red[i];
        tsx += r.x; tsxx += r.y; tsv += r.z; tsvv += r.w;
    }
    const float inv = 1.0f / DIMV;
    float mux = tsx * inv, varx = tsxx * inv - mux * mux;
    float muv = tsv * inv, varv = tsvv * inv - muv * muv;
    float rsx = rsqrtf(varx + EPSV);
    float rsv = rsqrtf(varv + EPSV);

    int d0 = tid * 4;
    const float4 gxp = *(const float4*)(lxg + d0);
    const float4 bxp = *(const float4*)(lxb + d0);
    const float4 gvp = *(const float4*)(lvg + d0);
    const float4 bvp = *(const float4*)(lvb + d0);

    float4 xn, vn;
    xn.x = (x4.x - mux) * rsx * gxp.x + bxp.x;
    xn.y = (x4.y - mux) * rsx * gxp.y + bxp.y;
    xn.z = (x4.z - mux) * rsx * gxp.z + bxp.z;
    xn.w = (x4.w - mux) * rsx * gxp.w + bxp.w;
    vn.x = (v4.x - muv) * rsv * gvp.x + bvp.x;
    vn.y = (v4.y - muv) * rsv * gvp.y + bvp.y;
    vn.z = (v4.z - muv) * rsv * gvp.z + bvp.z;
    vn.w = (v4.w - muv) * rsv * gvp.w + bvp.w;

    int h = tid >> 6;
    int c = (tid & 63) * 4;
    size_t base = ((size_t)h * NTOK + tok) * 512;
    *(float4*)(g_cat + base + c)       = xn;
    *(float4*)(g_cat + base + 256 + c) = vn;

    const float4 gwx = *(const float4*)(gw + h * 512 + c);
    const float4 gwv = *(const float4*)(gw + h * 512 + 256 + c);
    float gp = xn.x*gwx.x + xn.y*gwx.y + xn.z*gwx.z + xn.w*gwx.w
             + vn.x*gwv.x + vn.y*gwv.y + vn.z*gwv.z + vn.w*gwv.w;
    #pragma unroll
    for (int o = 16; o; o >>= 1) gp += __shfl_xor_sync(0xffffffffu, gp, o);
    __shared__ float gsh[8];
    if (lane == 0) gsh[w] = gp;
    __syncthreads();
    if (tid < NH) {
        float logit = gsh[2 * tid] + gsh[2 * tid + 1] + gb[tid];
        float gate = 1.0f / (1.0f + expf(-logit));
        float sp = log1pf(expf(dtp[tid]));
        g_dt[tok * NH + tid] = 2.0f * sp * gate;
    }
}

// =========================================================================
// tf32 tensor-core GEMM: 128x128x32 block (R11-proven), 256 threads,
// warp tile 32x64 (2x8 m16n8k8), cp.async double-buffered, dynamic smem.
// epi==0: C = sigmoid(A@B + bias[col]);  epi==1: C = aux + scale*(A@B)
// =========================================================================
#define GBM 128
#define GBN 128
#define GBK 32
#define AS_STRIDE 36
#define BS_STRIDE 136
#define A_ST_FLOATS (GBM * AS_STRIDE)
#define B_ST_FLOATS (GBK * BS_STRIDE)
#define GEMM_SMEM_BYTES (2 * (A_ST_FLOATS + B_ST_FLOATS) * 4)

#define ASM(s,r,k) Asm[(s)*A_ST_FLOATS + (r)*AS_STRIDE + (k)]
#define BSM(s,r,c) Bsm[(s)*B_ST_FLOATS + (r)*BS_STRIDE + (c)]

__global__ __launch_bounds__(256) void tgemm_tf32(
    const float* __restrict__ Ag, const float* __restrict__ Bg,
    const float* __restrict__ auxg, float* __restrict__ Cg,
    int M, int N, int K,
    long long sA, long long sB, long long sAux, long long sC,
    int epi, float scale)
{
    const int z = blockIdx.z;
    const float* A = Ag + (size_t)z * sA;
    const float* B = Bg + (size_t)z * sB;
    const float* AX = auxg + (size_t)z * sAux;
    float* C = Cg + (size_t)z * sC;

    extern __shared__ float smp[];
    float* Asm = smp;
    float* Bsm = smp + 2 * A_ST_FLOATS;

    const int tid = threadIdx.x;
    const int lane = tid & 31, w = tid >> 5;
    const int bx = blockIdx.x, by = blockIdx.y;

    const int wm = (w & 3) * 32;
    const int wn = (w >> 2) * 64;
    const int g  = lane >> 2;
    const int t4 = lane & 3;

    const int ar[4] = { tid >> 3, (tid + 256) >> 3, (tid + 512) >> 3, (tid + 768) >> 3 };
    const int ak = (tid & 7) * 4;
    const int br[4] = { tid >> 5, (tid + 256) >> 5, (tid + 512) >> 5, (tid + 768) >> 5 };
    const int bc = (tid & 31) * 4;

    const float* Ab = A + (size_t)(by * GBM) * K;
    const float* Bb = B + bx * GBN;

    const int KT = K / GBK;

    #define ISSUE(slot, ktile) do {                                              \
        int _k0 = (ktile) * GBK;                                                 \
        _Pragma("unroll")                                                        \
        for (int q = 0; q < 4; q++) {                                            \
            cp16(&ASM(slot, ar[q], ak), Ab + (size_t)ar[q] * K + _k0 + ak);      \
            cp16(&BSM(slot, br[q], bc), Bb + (size_t)(_k0 + br[q]) * N + bc);    \
        }                                                                        \
        CP_COMMIT();                                                             \
    } while (0)

    float acc[2][8][4];
    #pragma unroll
    for (int mt = 0; mt < 2; mt++)
        #pragma unroll
        for (int nt = 0; nt < 8; nt++)
            #pragma unroll
            for (int i = 0; i < 4; i++) acc[mt][nt][i] = 0.f;

    ISSUE(0, 0);

    for (int kt = 0; kt < KT; kt++) {
        const int s = kt & 1;
        if (kt + 1 < KT) {
            ISSUE((kt + 1) & 1, kt + 1);
        } else {
            CP_COMMIT();
        }
        CP_WAIT1();
        __syncthreads();

        #pragma unroll
        for (int kk = 0; kk < GBK; kk += 8) {
            float a[2][4];
            #pragma unroll
            for (int mt = 0; mt < 2; mt++) {
                int r0 = wm + mt * 16 + g;
                a[mt][0] = ASM(s, r0,     kk + t4);
                a[mt][1] = ASM(s, r0 + 8, kk + t4);
                a[mt][2] = ASM(s, r0,     kk + t4 + 4);
                a[mt][3] = ASM(s, r0 + 8, kk + t4 + 4);
            }
            float b[8][2];
            #pragma unroll
            for (int nt = 0; nt < 8; nt++) {
                int c0 = wn + nt * 8 + g;
                b[nt][0] = BSM(s, kk + t4,     c0);
                b[nt][1] = BSM(s, kk + t4 + 4, c0);
            }
            #pragma unroll
            for (int mt = 0; mt < 2; mt++)
                #pragma unroll
                for (int nt = 0; nt < 8; nt++)
                    mma_tf32(acc[mt][nt], a[mt], b[nt]);
        }
        __syncthreads();
    }

    #pragma unroll
    for (int mt = 0; mt < 2; mt++) {
        int r0 = by * GBM + wm + mt * 16 + g;
        #pragma unroll
        for (int nt = 0; nt < 8; nt++) {
            int c = bx * GBN + wn + nt * 8 + t4 * 2;
            size_t idx0 = (size_t)r0 * N + c;
            size_t idx1 = (size_t)(r0 + 8) * N + c;
            float2 o0, o1;
            if (epi == 0) {
                float b0 = AX[c], b1 = AX[c + 1];
                o0.x = 1.0f / (1.0f + expf(-(acc[mt][nt][0] + b0)));
                o0.y = 1.0f / (1.0f + expf(-(acc[mt][nt][1] + b1)));
                o1.x = 1.0f / (1.0f + expf(-(acc[mt][nt][2] + b0)));
                o1.y = 1.0f / (1.0f + expf(-(acc[mt][nt][3] + b1)));
            } else {
                float2 r0v = *(const float2*)(AX + idx0);
                float2 r1v = *(const float2*)(AX + idx1);
                o0.x = r0v.x + scale * acc[mt][nt][0];
                o0.y = r0v.y + scale * acc[mt][nt][1];
                o1.x = r1v.x + scale * acc[mt][nt][2];
                o1.y = r1v.y + scale * acc[mt][nt][3];
            }
            *(float2*)(C + idx0) = o0;
            *(float2*)(C + idx1) = o1;
        }
    }
    #undef ISSUE
}

// =========================================================================
// K3: Christoffel + Heun — R4 structure, but U/Wx staged in SHARED memory
// instead of per-thread registers (cuts ~32 regs → higher occupancy).
// vpr (16, per-thread-unique) stays in registers.
// =========================================================================
#define TOK3 16

__global__ __launch_bounds__(256) void k3_heun(
    const float* __restrict__ F,
    const float* __restrict__ U, const float* __restrict__ Wx,
    const float* __restrict__ Vp)
{
    const int h = blockIdx.y;
    const int tid = threadIdx.x, lane = tid & 31, w = tid >> 5;

    __shared__ float sv[256], sx[256], st[16];
    __shared__ __align__(16) float Us[16 * 256];
    __shared__ __align__(16) float Ws[16 * 256];

    // stage U, Wx for this head (16KB each)
    for (int i = tid; i < 16 * 256 / 4; i += 256) {
        ((float4*)Us)[i] = ((const float4*)(U  + h * 4096))[i];
        ((float4*)Ws)[i] = ((const float4*)(Wx + h * 4096))[i];
    }

    float vpr[16];
    #pragma unroll
    for (int r = 0; r < 16; r++) vpr[r] = Vp[h * 4096 + tid * 16 + r];

    const int r0 = 2 * w;
    const float* U0 = Us + r0 * 256;
    const float* U1 = Us + (r0 + 1) * 256;
    const float* W0 = Ws + r0 * 256;
    const float* W1 = Ws + (r0 + 1) * 256;

    __syncthreads();

    #define CHRIS(xq, vq, gvout) do {                                        \
        sv[tid] = (vq);                                                      \
        sx[tid] = (xq);                                                      \
        __syncthreads();                                                     \
        float c0 = 0.f, c1 = 0.f, g0 = 0.f, g1 = 0.f;                        \
        _Pragma("unroll")                                                    \
        for (int i = 0; i < 8; i++) {                                        \
            int ix = lane + 32 * i;                                          \
            float vv = sv[ix], xx = sx[ix];                                  \
            c0 += U0[ix] * vv; c1 += U1[ix] * vv;                            \
            g0 += W0[ix] * xx; g1 += W1[ix] * xx;                            \
        }                                                                    \
        _Pragma("unroll")                                                    \
        for (int o = 16; o; o >>= 1) {                                       \
            c0 += __shfl_xor_sync(0xffffffffu, c0, o);                       \
            c1 += __shfl_xor_sync(0xffffffffu, c1, o);                       \
            g0 += __shfl_xor_sync(0xffffffffu, g0, o);                       \
            g1 += __shfl_xor_sync(0xffffffffu, g1, o);                       \
        }                                                                    \
        if (lane == 0) {                                                     \
            st[2 * w]     = c0 * c0 * tanhf(g0);                             \
            st[2 * w + 1] = c1 * c1 * tanhf(g1);                             \
        }                                                                    \
        __syncthreads();                                                     \
        float gv = 0.f;                                                      \
        _Pragma("unroll")                                                    \
        for (int r = 0; r < 16; r++) gv += vpr[r] * st[r];                   \
        (gvout) = gv;                                                        \
        __syncthreads();                                                     \
    } while (0)

    for (int t = 0; t < TOK3; t++) {
        size_t tok = (size_t)blockIdx.x * TOK3 + t;
        float dt = g_dt[tok * NH + h];
        size_t cb = ((size_t)h * NTOK + tok) * 512;
        float xh = g_cat[cb + tid];
        float vh = g_cat[cb + 256 + tid];
        float Fd = F[tok * DIMV + h * HDV + tid];
        float gm = g_gamma[((size_t)h * NTOK + tok) * HDV + tid];

        float gv1;
        CHRIS(xh, vh, gv1);
        float k1v = Fd - gv1 - gm * vh;
        float xe = xh + dt * vh;
        float ve = vh + dt * k1v;
        float gv2;
        CHRIS(xe, ve, gv2);
        float k2v = Fd - gv2 - gm * ve;

        float xnew = xh + dt * vh + 0.5f * dt * dt * k1v;
        float vnew = vh + 0.5f * dt * (k1v + k2v);
        g_xvcat[tok * DIMV + h * HDV + tid] = tf32_rna(xnew);
        g_xvcat[(size_t)NTOK * DIMV + tok * DIMV + h * HDV + tid] = tf32_rna(vnew);
    }
    #undef CHRIS
}

// =========================================================================
// launch
// =========================================================================
extern "C" void kernel_launch(void* const* d_in, const int* in_sizes, int n_in,
                              void* d_out, int out_size)
{
    const float* x      = (const float*)d_in[0];
    const float* v      = (const float*)d_in[1];
    const float* F      = (const float*)d_in[2];
    const float* ln_x_g = (const float*)d_in[3];
    const float* ln_x_b = (const float*)d_in[4];
    const float* ln_v_g = (const float*)d_in[5];
    const float* ln_v_b = (const float*)d_in[6];
    const float* U      = (const float*)d_in[7];
    const float* Wx     = (const float*)d_in[8];
    const float* Vp     = (const float*)d_in[9];
    const float* gate_w = (const float*)d_in[10];
    const float* gate_b = (const float*)d_in[11];
    const float* fric_w = (const float*)d_in[12];
    const float* fric_b = (const float*)d_in[13];
    const float* dt_p   = (const float*)d_in[14];
    const float* Wo_x   = (const float*)d_in[15];
    const float* Wo_v   = (const float*)d_in[16];
    float* out = (float*)d_out;

    float *cat, *gamma, *xvcat, *wo;
    cudaGetSymbolAddress((void**)&cat,   g_cat);
    cudaGetSymbolAddress((void**)&gamma, g_gamma);
    cudaGetSymbolAddress((void**)&xvcat, g_xvcat);
    cudaGetSymbolAddress((void**)&wo,    g_wo);

    cudaFuncSetAttribute(tgemm_tf32,
                         cudaFuncAttributeMaxDynamicSharedMemorySize,
                         GEMM_SMEM_BYTES);

    // (1) K0: round both Wo weights to tf32
    {
        int n4h = DIMV * DIMV / 4;
        k0_round2<<<(n4h + 255) / 256, 256>>>(Wo_x, Wo_v, wo, n4h);
    }

    // (2) K1: LN + gate/dt + cat
    k1_ln_gate<<<NTOK, 256>>>(x, v, ln_x_g, ln_x_b, ln_v_g, ln_v_b,
                              gate_w, gate_b, dt_p);

    // (3) K2: friction gamma per head
    {
        dim3 grid(HDV / GBN, NTOK / GBM, NH);   // (1, 128, 4)
        tgemm_tf32<<<grid, 256, GEMM_SMEM_BYTES>>>(cat, fric_w, fric_b, gamma,
                                  NTOK, HDV, 2 * HDV,
                                  (long long)NTOK * 512, (long long)512 * HDV,
                                  (long long)HDV, (long long)NTOK * HDV,
                                  0, 0.0f);
    }

    // (4) K3: Christoffel + Heun (U/Wx in smem for occupancy)
    {
        dim3 grid(NTOK / TOK3, NH);   // (1024, 4)
        k3_heun<<<grid, 256>>>(F, U, Wx, Vp);
    }

    // (5)(6) K4: output projections + residual
    {
        dim3 grid(DIMV / GBN, NTOK / GBM, 1);   // (8, 128)
        tgemm_tf32<<<grid, 256, GEMM_SMEM_BYTES>>>(xvcat, wo, x, out,
                                  NTOK, DIMV, DIMV, 0, 0, 0, 0, 1, DEPTH_SCALE);
        tgemm_tf32<<<grid, 256, GEMM_SMEM_BYTES>>>(xvcat + (size_t)NTOK * DIMV,
                                  wo + (size_t)DIMV * DIMV, v,
                                  out + (size_t)NTOK * DIMV,
                                  NTOK, DIMV, DIMV, 0, 0, 0, 0, 1, DEPTH_SCALE);
    }
}

// round 13
// speedup vs baseline: 1.0879x; 1.0879x over previous
#include <cuda_runtime.h>
#include <math.h>
#include <stdint.h>

#define NTOK 16384
#define DIMV 1024
#define NH 4
#define HDV 256
#define EPSV 1e-5f
#define DEPTH_SCALE 0.40824829046386296f

// ---------------- scratch (device globals; no allocation) ----------------
__device__ __align__(16) float g_cat[(size_t)NH * NTOK * 512];     // [H][N][2HD]
__device__ __align__(16) float g_gamma[(size_t)NH * NTOK * HDV];   // [H][N][HD]
__device__ __align__(16) float g_dt[(size_t)NTOK * NH];            // [N][H]
__device__ __align__(16) float g_xvcat[(size_t)2 * NTOK * DIMV];   // x_cat then v_cat (tf32-rounded)
__device__ __align__(16) float g_wo[(size_t)2 * DIMV * DIMV];      // Wo_x, Wo_v tf32-rounded

// ---------------- tf32 helpers ----------------
__device__ __forceinline__ float tf32_rna(float x) {
    uint32_t u;
    asm("cvt.rna.tf32.f32 %0, %1;" : "=r"(u) : "f"(x));
    return __uint_as_float(u);
}

__device__ __forceinline__ void mma_tf32(float* d, const float* a, const float* b) {
    asm volatile(
        "mma.sync.aligned.m16n8k8.row.col.f32.tf32.tf32.f32 "
        "{%0,%1,%2,%3}, {%4,%5,%6,%7}, {%8,%9}, {%0,%1,%2,%3};\n"
        : "+f"(d[0]), "+f"(d[1]), "+f"(d[2]), "+f"(d[3])
        : "r"(__float_as_uint(a[0])), "r"(__float_as_uint(a[1])),
          "r"(__float_as_uint(a[2])), "r"(__float_as_uint(a[3])),
          "r"(__float_as_uint(b[0])), "r"(__float_as_uint(b[1])));
}

__device__ __forceinline__ void cp16(void* smem, const void* g) {
    uint32_t s = (uint32_t)__cvta_generic_to_shared(smem);
    asm volatile("cp.async.cg.shared.global [%0], [%1], 16;\n" :: "r"(s), "l"(g));
}
#define CP_COMMIT() asm volatile("cp.async.commit_group;\n" ::)
#define CP_WAIT1()  asm volatile("cp.async.wait_group 1;\n" ::)

// =========================================================================
// K0: round Wo_x and Wo_v to tf32 (RNA) into contiguous g_wo — ONE launch
// =========================================================================
__global__ __launch_bounds__(256) void k0_round2(const float* __restrict__ srcA,
                                                 const float* __restrict__ srcB,
                                                 float* __restrict__ dst, int n4half)
{
    int i = blockIdx.x * 256 + threadIdx.x;
    if (i < n4half) {
        float4 a = *(const float4*)(srcA + (size_t)i * 4);
        a.x = tf32_rna(a.x); a.y = tf32_rna(a.y);
        a.z = tf32_rna(a.z); a.w = tf32_rna(a.w);
        *(float4*)(dst + (size_t)i * 4) = a;
        float4 b = *(const float4*)(srcB + (size_t)i * 4);
        b.x = tf32_rna(b.x); b.y = tf32_rna(b.y);
        b.z = tf32_rna(b.z); b.w = tf32_rna(b.w);
        *(float4*)(dst + (size_t)n4half * 4 + (size_t)i * 4) = b;
    }
}

// =========================================================================
// K1: LayerNorm + gate (R4-proven block-per-token form)
// =========================================================================
__global__ __launch_bounds__(256) void k1_ln_gate(
    const float* __restrict__ x, const float* __restrict__ v,
    const float* __restrict__ lxg, const float* __restrict__ lxb,
    const float* __restrict__ lvg, const float* __restrict__ lvb,
    const float* __restrict__ gw, const float* __restrict__ gb,
    const float* __restrict__ dtp)
{
    size_t tok = blockIdx.x;
    int tid = threadIdx.x, lane = tid & 31, w = tid >> 5;

    const float4 x4 = *(const float4*)(x + tok * DIMV + tid * 4);
    const float4 v4 = *(const float4*)(v + tok * DIMV + tid * 4);

    float sx  = x4.x + x4.y + x4.z + x4.w;
    float sxx = x4.x*x4.x + x4.y*x4.y + x4.z*x4.z + x4.w*x4.w;
    float sv  = v4.x + v4.y + v4.z + v4.w;
    float svv = v4.x*v4.x + v4.y*v4.y + v4.z*v4.z + v4.w*v4.w;
    #pragma unroll
    for (int o = 16; o; o >>= 1) {
        sx  += __shfl_xor_sync(0xffffffffu, sx,  o);
        sxx += __shfl_xor_sync(0xffffffffu, sxx, o);
        sv  += __shfl_xor_sync(0xffffffffu, sv,  o);
        svv += __shfl_xor_sync(0xffffffffu, svv, o);
    }
    __shared__ float4 red[8];
    if (lane == 0) red[w] = make_float4(sx, sxx, sv, svv);
    __syncthreads();
    float tsx = 0.f, tsxx = 0.f, tsv = 0.f, tsvv = 0.f;
    #pragma unroll
    for (int i = 0; i < 8; i++) {
        float4 r = red[i];
        tsx += r.x; tsxx += r.y; tsv += r.z; tsvv += r.w;
    }
    const float inv = 1.0f / DIMV;
    float mux = tsx * inv, varx = tsxx * inv - mux * mux;
    float muv = tsv * inv, varv = tsvv * inv - muv * muv;
    float rsx = rsqrtf(varx + EPSV);
    float rsv = rsqrtf(varv + EPSV);

    int d0 = tid * 4;
    const float4 gxp = *(const float4*)(lxg + d0);
    const float4 bxp = *(const float4*)(lxb + d0);
    const float4 gvp = *(const float4*)(lvg + d0);
    const float4 bvp = *(const float4*)(lvb + d0);

    float4 xn, vn;
    xn.x = (x4.x - mux) * rsx * gxp.x + bxp.x;
    xn.y = (x4.y - mux) * rsx * gxp.y + bxp.y;
    xn.z = (x4.z - mux) * rsx * gxp.z + bxp.z;
    xn.w = (x4.w - mux) * rsx * gxp.w + bxp.w;
    vn.x = (v4.x - muv) * rsv * gvp.x + bvp.x;
    vn.y = (v4.y - muv) * rsv * gvp.y + bvp.y;
    vn.z = (v4.z - muv) * rsv * gvp.z + bvp.z;
    vn.w = (v4.w - muv) * rsv * gvp.w + bvp.w;

    int h = tid >> 6;
    int c = (tid & 63) * 4;
    size_t base = ((size_t)h * NTOK + tok) * 512;
    *(float4*)(g_cat + base + c)       = xn;
    *(float4*)(g_cat + base + 256 + c) = vn;

    const float4 gwx = *(const float4*)(gw + h * 512 + c);
    const float4 gwv = *(const float4*)(gw + h * 512 + 256 + c);
    float gp = xn.x*gwx.x + xn.y*gwx.y + xn.z*gwx.z + xn.w*gwx.w
             + vn.x*gwv.x + vn.y*gwv.y + vn.z*gwv.z + vn.w*gwv.w;
    #pragma unroll
    for (int o = 16; o; o >>= 1) gp += __shfl_xor_sync(0xffffffffu, gp, o);
    __shared__ float gsh[8];
    if (lane == 0) gsh[w] = gp;
    __syncthreads();
    if (tid < NH) {
        float logit = gsh[2 * tid] + gsh[2 * tid + 1] + gb[tid];
        float gate = 1.0f / (1.0f + expf(-logit));
        float sp = log1pf(expf(dtp[tid]));
        g_dt[tok * NH + tid] = 2.0f * sp * gate;
    }
}

// =========================================================================
// tf32 tensor-core GEMM: 128x128x32 block (R11-proven), dynamic smem.
// epi==0: C = sigmoid(A@B + bias[col]), bias = auxA + z*sAux
// epi==1: C = aux + scale*(A@B),        aux  = (z==0 ? auxA : auxB)
// =========================================================================
#define GBM 128
#define GBN 128
#define GBK 32
#define AS_STRIDE 36
#define BS_STRIDE 136
#define A_ST_FLOATS (GBM * AS_STRIDE)
#define B_ST_FLOATS (GBK * BS_STRIDE)
#define GEMM_SMEM_BYTES (2 * (A_ST_FLOATS + B_ST_FLOATS) * 4)

#define ASM(s,r,k) Asm[(s)*A_ST_FLOATS + (r)*AS_STRIDE + (k)]
#define BSM(s,r,c) Bsm[(s)*B_ST_FLOATS + (r)*BS_STRIDE + (c)]

__global__ __launch_bounds__(256) void tgemm_tf32(
    const float* __restrict__ Ag, const float* __restrict__ Bg,
    const float* __restrict__ auxA, const float* __restrict__ auxB,
    float* __restrict__ Cg,
    int M, int N, int K,
    long long sA, long long sB, long long sAux, long long sC,
    int epi, float scale)
{
    const int z = blockIdx.z;
    const float* A = Ag + (size_t)z * sA;
    const float* B = Bg + (size_t)z * sB;
    const float* AX = (epi == 0) ? (auxA + (size_t)z * sAux)
                                 : (z ? auxB : auxA);
    float* C = Cg + (size_t)z * sC;

    extern __shared__ float smp[];
    float* Asm = smp;
    float* Bsm = smp + 2 * A_ST_FLOATS;

    const int tid = threadIdx.x;
    const int lane = tid & 31, w = tid >> 5;
    const int bx = blockIdx.x, by = blockIdx.y;

    const int wm = (w & 3) * 32;
    const int wn = (w >> 2) * 64;
    const int g  = lane >> 2;
    const int t4 = lane & 3;

    const int ar[4] = { tid >> 3, (tid + 256) >> 3, (tid + 512) >> 3, (tid + 768) >> 3 };
    const int ak = (tid & 7) * 4;
    const int br[4] = { tid >> 5, (tid + 256) >> 5, (tid + 512) >> 5, (tid + 768) >> 5 };
    const int bc = (tid & 31) * 4;

    const float* Ab = A + (size_t)(by * GBM) * K;
    const float* Bb = B + bx * GBN;

    const int KT = K / GBK;

    #define ISSUE(slot, ktile) do {                                              \
        int _k0 = (ktile) * GBK;                                                 \
        _Pragma("unroll")                                                        \
        for (int q = 0; q < 4; q++) {                                            \
            cp16(&ASM(slot, ar[q], ak), Ab + (size_t)ar[q] * K + _k0 + ak);      \
            cp16(&BSM(slot, br[q], bc), Bb + (size_t)(_k0 + br[q]) * N + bc);    \
        }                                                                        \
        CP_COMMIT();                                                             \
    } while (0)

    float acc[2][8][4];
    #pragma unroll
    for (int mt = 0; mt < 2; mt++)
        #pragma unroll
        for (int nt = 0; nt < 8; nt++)
            #pragma unroll
            for (int i = 0; i < 4; i++) acc[mt][nt][i] = 0.f;

    ISSUE(0, 0);

    for (int kt = 0; kt < KT; kt++) {
        const int s = kt & 1;
        if (kt + 1 < KT) {
            ISSUE((kt + 1) & 1, kt + 1);
        } else {
            CP_COMMIT();
        }
        CP_WAIT1();
        __syncthreads();

        #pragma unroll
        for (int kk = 0; kk < GBK; kk += 8) {
            float a[2][4];
            #pragma unroll
            for (int mt = 0; mt < 2; mt++) {
                int r0 = wm + mt * 16 + g;
                a[mt][0] = ASM(s, r0,     kk + t4);
                a[mt][1] = ASM(s, r0 + 8, kk + t4);
                a[mt][2] = ASM(s, r0,     kk + t4 + 4);
                a[mt][3] = ASM(s, r0 + 8, kk + t4 + 4);
            }
            float b[8][2];
            #pragma unroll
            for (int nt = 0; nt < 8; nt++) {
                int c0 = wn + nt * 8 + g;
                b[nt][0] = BSM(s, kk + t4,     c0);
                b[nt][1] = BSM(s, kk + t4 + 4, c0);
            }
            #pragma unroll
            for (int mt = 0; mt < 2; mt++)
                #pragma unroll
                for (int nt = 0; nt < 8; nt++)
                    mma_tf32(acc[mt][nt], a[mt], b[nt]);
        }
        __syncthreads();
    }

    #pragma unroll
    for (int mt = 0; mt < 2; mt++) {
        int r0 = by * GBM + wm + mt * 16 + g;
        #pragma unroll
        for (int nt = 0; nt < 8; nt++) {
            int c = bx * GBN + wn + nt * 8 + t4 * 2;
            size_t idx0 = (size_t)r0 * N + c;
            size_t idx1 = (size_t)(r0 + 8) * N + c;
            float2 o0, o1;
            if (epi == 0) {
                float b0 = AX[c], b1 = AX[c + 1];
                o0.x = 1.0f / (1.0f + expf(-(acc[mt][nt][0] + b0)));
                o0.y = 1.0f / (1.0f + expf(-(acc[mt][nt][1] + b1)));
                o1.x = 1.0f / (1.0f + expf(-(acc[mt][nt][2] + b0)));
                o1.y = 1.0f / (1.0f + expf(-(acc[mt][nt][3] + b1)));
            } else {
                float2 r0v = *(const float2*)(AX + idx0);
                float2 r1v = *(const float2*)(AX + idx1);
                o0.x = r0v.x + scale * acc[mt][nt][0];
                o0.y = r0v.y + scale * acc[mt][nt][1];
                o1.x = r1v.x + scale * acc[mt][nt][2];
                o1.y = r1v.y + scale * acc[mt][nt][3];
            }
            *(float2*)(C + idx0) = o0;
            *(float2*)(C + idx1) = o1;
        }
    }
    #undef ISSUE
}

// =========================================================================
// K3: Christoffel + Heun — R11-proven register form, TOK3=32 (halved
// block count → halved preload traffic + tail waves).
// =========================================================================
#define TOK3 32

__device__ __forceinline__ float christoffel(
    float* sv, float* sx, float* st,
    float xq, float vq,
    const float Ur0[8], const float Ur1[8],
    const float Wr0[8], const float Wr1[8],
    const float vpr[16],
    int lane, int w, int tid)
{
    sv[tid] = vq;
    sx[tid] = xq;
    __syncthreads();
    float c0 = 0.f, c1 = 0.f, g0 = 0.f, g1 = 0.f;
    #pragma unroll
    for (int i = 0; i < 8; i++) {
        float vv = sv[lane + 32 * i];
        float xx = sx[lane + 32 * i];
        c0 += Ur0[i] * vv; c1 += Ur1[i] * vv;
        g0 += Wr0[i] * xx; g1 += Wr1[i] * xx;
    }
    #pragma unroll
    for (int o = 16; o; o >>= 1) {
        c0 += __shfl_xor_sync(0xffffffffu, c0, o);
        c1 += __shfl_xor_sync(0xffffffffu, c1, o);
        g0 += __shfl_xor_sync(0xffffffffu, g0, o);
        g1 += __shfl_xor_sync(0xffffffffu, g1, o);
    }
    if (lane == 0) {
        st[2 * w]     = c0 * c0 * tanhf(g0);
        st[2 * w + 1] = c1 * c1 * tanhf(g1);
    }
    __syncthreads();
    float gv = 0.f;
    #pragma unroll
    for (int r = 0; r < 16; r++) gv += vpr[r] * st[r];
    return gv;
}

__global__ __launch_bounds__(256) void k3_heun(
    const float* __restrict__ F,
    const float* __restrict__ U, const float* __restrict__ Wx,
    const float* __restrict__ Vp)
{
    const int h = blockIdx.y;
    const int tid = threadIdx.x, lane = tid & 31, w = tid >> 5;

    __shared__ float sv[256], sx[256], st[16];

    float Ur0[8], Ur1[8], Wr0[8], Wr1[8];
    const int r0 = 2 * w;
    #pragma unroll
    for (int i = 0; i < 8; i++) {
        Ur0[i] = U[h * 4096 + r0 * 256 + lane + 32 * i];
        Ur1[i] = U[h * 4096 + (r0 + 1) * 256 + lane + 32 * i];
        Wr0[i] = Wx[h * 4096 + r0 * 256 + lane + 32 * i];
        Wr1[i] = Wx[h * 4096 + (r0 + 1) * 256 + lane + 32 * i];
    }
    float vpr[16];
    #pragma unroll
    for (int r = 0; r < 16; r++) vpr[r] = Vp[h * 4096 + tid * 16 + r];

    for (int t = 0; t < TOK3; t++) {
        size_t tok = (size_t)blockIdx.x * TOK3 + t;
        float dt = g_dt[tok * NH + h];
        size_t cb = ((size_t)h * NTOK + tok) * 512;
        float xh = g_cat[cb + tid];
        float vh = g_cat[cb + 256 + tid];
        float Fd = F[tok * DIMV + h * HDV + tid];
        float gm = g_gamma[((size_t)h * NTOK + tok) * HDV + tid];

        float gv1 = christoffel(sv, sx, st, xh, vh, Ur0, Ur1, Wr0, Wr1, vpr, lane, w, tid);
        float k1v = Fd - gv1 - gm * vh;
        float xe = xh + dt * vh;
        float ve = vh + dt * k1v;
        float gv2 = christoffel(sv, sx, st, xe, ve, Ur0, Ur1, Wr0, Wr1, vpr, lane, w, tid);
        float k2v = Fd - gv2 - gm * ve;

        float xnew = xh + dt * vh + 0.5f * dt * dt * k1v;
        float vnew = vh + 0.5f * dt * (k1v + k2v);
        g_xvcat[tok * DIMV + h * HDV + tid] = tf32_rna(xnew);
        g_xvcat[(size_t)NTOK * DIMV + tok * DIMV + h * HDV + tid] = tf32_rna(vnew);
    }
}

// =========================================================================
// launch
// =========================================================================
extern "C" void kernel_launch(void* const* d_in, const int* in_sizes, int n_in,
                              void* d_out, int out_size)
{
    const float* x      = (const float*)d_in[0];
    const float* v      = (const float*)d_in[1];
    const float* F      = (const float*)d_in[2];
    const float* ln_x_g = (const float*)d_in[3];
    const float* ln_x_b = (const float*)d_in[4];
    const float* ln_v_g = (const float*)d_in[5];
    const float* ln_v_b = (const float*)d_in[6];
    const float* U      = (const float*)d_in[7];
    const float* Wx     = (const float*)d_in[8];
    const float* Vp     = (const float*)d_in[9];
    const float* gate_w = (const float*)d_in[10];
    const float* gate_b = (const float*)d_in[11];
    const float* fric_w = (const float*)d_in[12];
    const float* fric_b = (const float*)d_in[13];
    const float* dt_p   = (const float*)d_in[14];
    const float* Wo_x   = (const float*)d_in[15];
    const float* Wo_v   = (const float*)d_in[16];
    float* out = (float*)d_out;

    float *cat, *gamma, *xvcat, *wo;
    cudaGetSymbolAddress((void**)&cat,   g_cat);
    cudaGetSymbolAddress((void**)&gamma, g_gamma);
    cudaGetSymbolAddress((void**)&xvcat, g_xvcat);
    cudaGetSymbolAddress((void**)&wo,    g_wo);

    cudaFuncSetAttribute(tgemm_tf32,
                         cudaFuncAttributeMaxDynamicSharedMemorySize,
                         GEMM_SMEM_BYTES);

    // (1) K0: round both Wo weights to tf32
    {
        int n4h = DIMV * DIMV / 4;
        k0_round2<<<(n4h + 255) / 256, 256>>>(Wo_x, Wo_v, wo, n4h);
    }

    // (2) K1: LN + gate/dt + cat
    k1_ln_gate<<<NTOK, 256>>>(x, v, ln_x_g, ln_x_b, ln_v_g, ln_v_b,
                              gate_w, gate_b, dt_p);

    // (3) K2: friction gamma per head
    {
        dim3 grid(HDV / GBN, NTOK / GBM, NH);   // (2, 128, 4)
        tgemm_tf32<<<grid, 256, GEMM_SMEM_BYTES>>>(cat, fric_w, fric_b,
                                  (const float*)0, gamma,
                                  NTOK, HDV, 2 * HDV,
                                  (long long)NTOK * 512, (long long)512 * HDV,
                                  (long long)HDV, (long long)NTOK * HDV,
                                  0, 0.0f);
    }

    // (4) K3: Christoffel + Heun (R11 register form, TOK3=32)
    {
        dim3 grid(NTOK / TOK3, NH);   // (512, 4)
        k3_heun<<<grid, 256>>>(F, U, Wx, Vp);
    }

    // (5) K4: both output projections in ONE launch (grid.z = 2)
    {
        dim3 grid(DIMV / GBN, NTOK / GBM, 2);   // (8, 128, 2)
        tgemm_tf32<<<grid, 256, GEMM_SMEM_BYTES>>>(xvcat, wo, x, v, out,
                                  NTOK, DIMV, DIMV,
                                  (long long)NTOK * DIMV,
                                  (long long)DIMV * DIMV,
                                  0,
                                  (long long)NTOK * DIMV,
                                  1, DEPTH_SCALE);
    }
}